// round 15
// baseline (speedup 1.0000x reference)
#include <cuda_runtime.h>
#include <cuda_bf16.h>
#include <cstdint>

#define BB 256
#define TT 256
#define DD 64
#define HH 256
#define GG 768

// ---------------- scratch ----------------
__device__ float    g_XT[TT * BB * DD];
__device__ float    g_H1[TT * BB * 2 * HH];
__device__ float    g_GI[2 * TT * BB * GG];
__device__ unsigned g_Whi[16 * 24576];   // [l*2+d][rank] -> frag-ordered bf16x2 words (hi)
__device__ unsigned g_Wlo[16 * 24576];   // (lo)

// ---------------- helpers ----------------
__device__ __forceinline__ float sigmoidf_fast(float x) {
    return 1.0f / (1.0f + __expf(-x));
}
__device__ __forceinline__ unsigned cvt_tf32(float f) {
    unsigned r;
    asm volatile("cvt.rna.tf32.f32 %0, %1;" : "=r"(r) : "f"(f));
    return r;
}
__device__ __forceinline__ unsigned mapa_sh(unsigned addr, unsigned rnk) {
    unsigned ra;
    asm volatile("mapa.shared::cluster.u32 %0, %1, %2;" : "=r"(ra) : "r"(addr), "r"(rnk));
    return ra;
}
#define CLUSTER_SYNC_() \
    asm volatile("barrier.cluster.arrive.aligned;\n\tbarrier.cluster.wait.aligned;" ::: "memory")

__device__ __forceinline__ void mbar_init(unsigned addr, unsigned cnt) {
    asm volatile("mbarrier.init.shared.b64 [%0], %1;" :: "r"(addr), "r"(cnt) : "memory");
}
__device__ __forceinline__ void mbar_arrive_rank(unsigned remaddr) {
    asm volatile("mbarrier.arrive.shared::cluster.b64 _, [%0];" :: "r"(remaddr) : "memory");
}
__device__ __forceinline__ void mbar_wait_cluster(unsigned addr, unsigned parity) {
    unsigned done;
    do {
        asm volatile(
            "{\n\t.reg .pred p;\n\t"
            "mbarrier.try_wait.parity.acquire.cluster.shared::cta.b64 p, [%1], %2, 0x989680;\n\t"
            "selp.b32 %0, 1, 0, p;\n\t}"
            : "=r"(done) : "r"(addr), "r"(parity) : "memory");
    } while (!done);
}

__device__ __forceinline__ void mma_tf32(float* acc, const unsigned* a, unsigned b0, unsigned b1) {
    asm volatile(
        "mma.sync.aligned.m16n8k8.row.col.f32.tf32.tf32.f32 "
        "{%0,%1,%2,%3}, {%4,%5,%6,%7}, {%8,%9}, {%0,%1,%2,%3};\n"
        : "+f"(acc[0]), "+f"(acc[1]), "+f"(acc[2]), "+f"(acc[3])
        : "r"(a[0]), "r"(a[1]), "r"(a[2]), "r"(a[3]), "r"(b0), "r"(b1));
}
__device__ __forceinline__ void mma_bf16(float* acc, const unsigned* a, unsigned b0, unsigned b1) {
    asm volatile(
        "mma.sync.aligned.m16n8k16.row.col.f32.bf16.bf16.f32 "
        "{%0,%1,%2,%3}, {%4,%5,%6,%7}, {%8,%9}, {%0,%1,%2,%3};\n"
        : "+f"(acc[0]), "+f"(acc[1]), "+f"(acc[2]), "+f"(acc[3])
        : "r"(a[0]), "r"(a[1]), "r"(a[2]), "r"(a[3]), "r"(b0), "r"(b1));
}

// ---------------- transpose x ----------------
__global__ void transpose_x(const float* __restrict__ x) {
    int i = blockIdx.x * blockDim.x + threadIdx.x;
    if (i >= BB * TT * (DD / 4)) return;
    int d4 = i & 15;
    int t  = (i >> 4) & 255;
    int b  = i >> 12;
    const float4* src = reinterpret_cast<const float4*>(x);
    float4* dst = reinterpret_cast<float4*>(g_XT);
    dst[((t * BB + b) * (DD / 4)) + d4] = src[((b * TT + t) * (DD / 4)) + d4];
}

// ---------------- prep: split w_hh into fragment-ordered bf16 hi/lo planes ----------------
__global__ void prep_wsplit(const float* __restrict__ w0, const float* __restrict__ w1) {
    int i = blockIdx.x * blockDim.x + threadIdx.x;
    if (i >= 16 * 24576) return;
    int w64  = i & 63;
    int blk  = i >> 6;
    int kf   = blk & 15;
    int gfid = blk >> 4;
    int gf   = gfid % 24;
    int ldr  = gfid / 24;
    int rank = ldr & 3;
    int d    = (ldr >> 2) & 1;
    int l    = ldr >> 3;
    int g    = gf >> 3;
    int f    = gf & 7;
    int lane = w64 >> 1;
    int r    = w64 & 1;
    int row  = g * 256 + rank * 64 + f * 8 + (lane >> 2);
    int k    = kf * 16 + (lane & 3) * 2 + r * 8;
    const float* w = l ? w1 : w0;
    const float* p = w + ((size_t)d * GG + row) * HH + k;
    float v0 = p[0], v1 = p[1];
    __nv_bfloat16 h0 = __float2bfloat16(v0);
    __nv_bfloat16 h1 = __float2bfloat16(v1);
    __nv_bfloat16 l0 = __float2bfloat16(v0 - __bfloat162float(h0));
    __nv_bfloat16 l1 = __float2bfloat16(v1 - __bfloat162float(h1));
    g_Whi[i] = ((unsigned)__bfloat16_as_ushort(h1) << 16) | __bfloat16_as_ushort(h0);
    g_Wlo[i] = ((unsigned)__bfloat16_as_ushort(l1) << 16) | __bfloat16_as_ushort(l0);
}

// ---------------- gi GEMM: tf32x3, 128x128 tiles (validated, unchanged) ----------------
#define Bb_M 128
#define Bb_N 128
#define Bb_K 16
#define SSTR 20

__global__ void __launch_bounds__(256) gemm_tf32(int layer,
                                                 const float* __restrict__ Wih,
                                                 const float* __restrict__ bih,
                                                 const float* __restrict__ bhh) {
    __shared__ float sA[2][Bb_M * SSTR];
    __shared__ float sB[2][Bb_N * SSTR];

    const float* A = layer ? g_H1 : g_XT;
    const int K    = layer ? 512 : 64;
    float* C = g_GI;

    int tid  = threadIdx.x;
    int m0   = blockIdx.x * Bb_M;
    int n0   = blockIdx.y * Bb_N;
    int d    = blockIdx.z;
    const float* Ab = A + (size_t)m0 * K;
    const float* Wb = Wih + ((size_t)d * GG + n0) * K;
    float* Cb = C + (size_t)d * (TT * BB) * GG;

    int lane = tid & 31, wid = tid >> 5;
    int wm = wid & 3, wn = wid >> 2;

    float acc[2][8][4];
#pragma unroll
    for (int a = 0; a < 2; a++)
#pragma unroll
        for (int b = 0; b < 8; b++)
#pragma unroll
            for (int c = 0; c < 4; c++) acc[a][b][c] = 0.0f;

    auto load_tile = [&](int kt, int buf) {
        int k0 = kt * Bb_K;
#pragma unroll
        for (int i = 0; i < 2; i++) {
            int s   = tid * 2 + i;
            int row = s >> 2;
            int seg = s & 3;
            unsigned da = (unsigned)__cvta_generic_to_shared(&sA[buf][row * SSTR + seg * 4]);
            const float* ga = Ab + (size_t)row * K + k0 + seg * 4;
            asm volatile("cp.async.cg.shared.global [%0], [%1], 16;\n" :: "r"(da), "l"(ga));
            unsigned db = (unsigned)__cvta_generic_to_shared(&sB[buf][row * SSTR + seg * 4]);
            const float* gb = Wb + (size_t)row * K + k0 + seg * 4;
            asm volatile("cp.async.cg.shared.global [%0], [%1], 16;\n" :: "r"(db), "l"(gb));
        }
        asm volatile("cp.async.commit_group;\n" ::: "memory");
    };

    const int KT = K / Bb_K;
    load_tile(0, 0);
    for (int kt = 0; kt < KT; kt++) {
        int buf = kt & 1;
        if (kt + 1 < KT) {
            load_tile(kt + 1, buf ^ 1);
            asm volatile("cp.async.wait_group 1;\n" ::: "memory");
        } else {
            asm volatile("cp.async.wait_group 0;\n" ::: "memory");
        }
        __syncthreads();
        const float* a_s = sA[buf];
        const float* b_s = sB[buf];
#pragma unroll
        for (int ks = 0; ks < 2; ks++) {
            int kk = ks * 8;
            unsigned ahi[2][4], alo[2][4];
#pragma unroll
            for (int mf = 0; mf < 2; mf++) {
                const float* p = a_s + (wm * 32 + mf * 16 + (lane >> 2)) * SSTR + kk + (lane & 3);
                float f0 = p[0];
                float f1 = p[8 * SSTR];
                float f2 = p[4];
                float f3 = p[8 * SSTR + 4];
                ahi[mf][0] = cvt_tf32(f0); alo[mf][0] = __float_as_uint(f0 - __uint_as_float(ahi[mf][0]));
                ahi[mf][1] = cvt_tf32(f1); alo[mf][1] = __float_as_uint(f1 - __uint_as_float(ahi[mf][1]));
                ahi[mf][2] = cvt_tf32(f2); alo[mf][2] = __float_as_uint(f2 - __uint_as_float(ahi[mf][2]));
                ahi[mf][3] = cvt_tf32(f3); alo[mf][3] = __float_as_uint(f3 - __uint_as_float(ahi[mf][3]));
            }
#pragma unroll
            for (int nf = 0; nf < 8; nf++) {
                const float* p = b_s + (wn * 64 + nf * 8 + (lane >> 2)) * SSTR + kk + (lane & 3);
                float g0 = p[0];
                float g1 = p[4];
                unsigned bhi0 = cvt_tf32(g0), blo0 = __float_as_uint(g0 - __uint_as_float(bhi0));
                unsigned bhi1 = cvt_tf32(g1), blo1 = __float_as_uint(g1 - __uint_as_float(bhi1));
#pragma unroll
                for (int mf = 0; mf < 2; mf++) {
                    mma_tf32(acc[mf][nf], ahi[mf], bhi0, bhi1);
                    mma_tf32(acc[mf][nf], ahi[mf], blo0, blo1);
                    mma_tf32(acc[mf][nf], alo[mf], bhi0, bhi1);
                }
            }
        }
        __syncthreads();
    }

#pragma unroll
    for (int mf = 0; mf < 2; mf++)
#pragma unroll
        for (int nf = 0; nf < 8; nf++)
#pragma unroll
            for (int i = 0; i < 4; i++) {
                int row = m0 + wm * 32 + mf * 16 + (lane >> 2) + ((i >> 1) ? 8 : 0);
                int col = n0 + wn * 64 + nf * 8 + (lane & 3) * 2 + (i & 1);
                float bias = __ldg(&bih[d * GG + col]) +
                             (col < 2 * HH ? __ldg(&bhh[d * GG + col]) : 0.0f);
                Cb[(size_t)row * GG + col] = acc[mf][nf][i] + bias;
            }
}

// ---------------- GRU scan v9: TWO interleaved batch groups hide cluster latency ----
// Cluster of 4 CTAs = (dir, 32-batch chunk) split into groups A(16) and B(16), each
// an independent recurrence with its own single h buffer + (reads, writes) barrier
// pair (v6-proven protocol). Per step: A-compute, A-store, B-compute, B-store —
// every cluster wait has a full other-group phase between the matching remote
// arrival and the wait, hiding the handshake round-trip behind real work.
// Gating uses the v8-verified shuffle regather (no staging smem).
#define WPL_W   24576
#define HPL     8448                        // bytes per h plane (16*132 words)
#define WH_OFF  0
#define WL_OFF  (WPL_W * 4)                 // 98304
#define H_OFF   (2 * WPL_W * 4)             // 196608; per group: [hi][lo] = 2*HPL
#define MB_OFF  (H_OFF + 2 * 2 * HPL)       // 230400; per group: reads@+g*16, writes@+g*16+8
#define SMEM_SCAN (MB_OFF + 32)             // 230432

__global__ void __launch_bounds__(256, 1) __cluster_dims__(4, 1, 1)
gru_scan_mma(int layer, const float* __restrict__ bhh, float* __restrict__ fin) {
    extern __shared__ char smem[];
    unsigned* Wh = reinterpret_cast<unsigned*>(smem + WH_OFF);
    unsigned* Wl = reinterpret_cast<unsigned*>(smem + WL_OFF);

    int tid  = threadIdx.x;
    int lane = tid & 31;
    int w    = tid >> 5;
    int rank = blockIdx.x & 3;
    int cid  = blockIdx.x >> 2;
    int d    = cid & 1;
    int b0   = (cid >> 1) * 32;            // 32 batches per cluster

    // load W planes
    {
        const uint4* shi = reinterpret_cast<const uint4*>(g_Whi + (size_t)((layer * 2 + d) * 4 + rank) * WPL_W);
        const uint4* slo = reinterpret_cast<const uint4*>(g_Wlo + (size_t)((layer * 2 + d) * 4 + rank) * WPL_W);
        uint4* dhi = reinterpret_cast<uint4*>(Wh);
        uint4* dlo = reinterpret_cast<uint4*>(Wl);
#pragma unroll 4
        for (int i = tid; i < WPL_W / 4; i += 256) { dhi[i] = shi[i]; dlo[i] = slo[i]; }
    }
    // zero both groups' h planes (2 groups x 2 planes x 2112 words)
    {
        unsigned* hz = reinterpret_cast<unsigned*>(smem + H_OFF);
        for (int i = tid; i < 4 * 2112; i += 256) hz[i] = 0u;
    }

    unsigned smbase = (unsigned)__cvta_generic_to_shared(smem);
    if (tid == 0) {
#pragma unroll
        for (int g = 0; g < 2; g++) {
            mbar_init(smbase + MB_OFF + g * 16, 4);       // reads
            mbar_init(smbase + MB_OFF + g * 16 + 8, 4);   // writes
        }
    }

    // ownership (warp-local): warp w, pb = lane&15 (within group), jhalf = lane>>4
    int pb     = lane & 15;
    int jhalf  = lane >> 4;
    int jl4    = w * 8 + jhalf * 4;
    int jg4    = rank * 64 + jl4;
    float4 bn4 = *reinterpret_cast<const float4*>(&bhh[d * GG + 2 * HH + jg4]);

    CLUSTER_SYNC_();   // once: smem + mbarrier init visible cluster-wide

    unsigned ra[4];
    ra[0] = mapa_sh(smbase, 0);
    ra[1] = mapa_sh(smbase, 1);
    ra[2] = mapa_sh(smbase, 2);
    ra[3] = mapa_sh(smbase, 3);

    // hoisted remote barrier addresses per group
    unsigned rd0[2], rd1[2], rd2[2], rd3[2], wr0[2], wr1[2], wr2[2], wr3[2];
#pragma unroll
    for (int g = 0; g < 2; g++) {
        rd0[g] = ra[0] + MB_OFF + g * 16;     rd1[g] = ra[1] + MB_OFF + g * 16;
        rd2[g] = ra[2] + MB_OFF + g * 16;     rd3[g] = ra[3] + MB_OFF + g * 16;
        wr0[g] = rd0[g] + 8;  wr1[g] = rd1[g] + 8;
        wr2[g] = rd2[g] + 8;  wr3[g] = rd3[g] + 8;
    }

    int ar = lane >> 2;
    int aw = ar * 132 + (lane & 3);
    int bR = ((0 * 8 + w) * 16) * 64 + lane * 2;
    int bZ = ((1 * 8 + w) * 16) * 64 + lane * 2;
    int bN = ((2 * 8 + w) * 16) * 64 + lane * 2;

    unsigned hw0 = (unsigned)(pb * 132 + (jg4 >> 1));

    // shuffle-regather constants (v8-verified)
    int s0   = (pb & 7) * 4 + jhalf * 2;
    int s1   = s0 + 1;
    bool hiP = (pb >> 3) != 0;

    float hn[2][4];
#pragma unroll
    for (int g = 0; g < 2; g++)
#pragma unroll
        for (int i = 0; i < 4; i++) hn[g][i] = 0.f;

    for (int s = 0; s < TT; s++) {
        int t = d ? (TT - 1 - s) : s;

#pragma unroll
        for (int g = 0; g < 2; g++) {
            unsigned mbR_l = smbase + MB_OFF + g * 16;
            unsigned mbW_l = smbase + MB_OFF + g * 16 + 8;
            unsigned hoff  = (unsigned)(H_OFF + g * 2 * HPL);
            const unsigned* hhi = reinterpret_cast<const unsigned*>(smem + hoff);
            const unsigned* hlo = reinterpret_cast<const unsigned*>(smem + hoff + HPL);

            // ---- compute phase ----
            if (s) mbar_wait_cluster(mbW_l, (s & 1) ^ 1);   // h_g(s) visible

            const float* gib = g_GI + ((size_t)d * (TT * BB) + (size_t)t * BB + b0 + g * 16 + pb) * GG;
            float4 gir = *reinterpret_cast<const float4*>(gib + jg4);
            float4 giz = *reinterpret_cast<const float4*>(gib + 256 + jg4);
            float4 gin = *reinterpret_cast<const float4*>(gib + 512 + jg4);

            float accR[4] = {0.f, 0.f, 0.f, 0.f};
            float accZ[4] = {0.f, 0.f, 0.f, 0.f};
            float accN[4] = {0.f, 0.f, 0.f, 0.f};

#pragma unroll
            for (int kf = 0; kf < 16; kf++) {
                unsigned ahi[4], alo[4];
                ahi[0] = hhi[aw + kf * 8];
                ahi[1] = hhi[aw + kf * 8 + 1056];
                ahi[2] = hhi[aw + kf * 8 + 4];
                ahi[3] = hhi[aw + kf * 8 + 1060];
                alo[0] = hlo[aw + kf * 8];
                alo[1] = hlo[aw + kf * 8 + 1056];
                alo[2] = hlo[aw + kf * 8 + 4];
                alo[3] = hlo[aw + kf * 8 + 1060];

                uint2 bh, bl;
                bh = *reinterpret_cast<const uint2*>(&Wh[bR + kf * 64]);
                bl = *reinterpret_cast<const uint2*>(&Wl[bR + kf * 64]);
                mma_bf16(accR, ahi, bh.x, bh.y);
                mma_bf16(accR, ahi, bl.x, bl.y);
                mma_bf16(accR, alo, bh.x, bh.y);

                bh = *reinterpret_cast<const uint2*>(&Wh[bZ + kf * 64]);
                bl = *reinterpret_cast<const uint2*>(&Wl[bZ + kf * 64]);
                mma_bf16(accZ, ahi, bh.x, bh.y);
                mma_bf16(accZ, ahi, bl.x, bl.y);
                mma_bf16(accZ, alo, bh.x, bh.y);

                bh = *reinterpret_cast<const uint2*>(&Wh[bN + kf * 64]);
                bl = *reinterpret_cast<const uint2*>(&Wl[bN + kf * 64]);
                mma_bf16(accN, ahi, bh.x, bh.y);
                mma_bf16(accN, ahi, bl.x, bl.y);
                mma_bf16(accN, alo, bh.x, bh.y);
            }

            __syncthreads();   // this CTA done reading h_g(s)
            if (tid == 0 && s + 1 < TT) {
                mbar_arrive_rank(rd0[g]);
                mbar_arrive_rank(rd1[g]);
                mbar_arrive_rank(rd2[g]);
                mbar_arrive_rank(rd3[g]);
            }

            // shuffle regather (v8-verified mapping)
            float4 sR, sZ, sN;
            {
                float a0, a1, a2, a3;
                a0 = __shfl_sync(0xFFFFFFFFu, accR[0], s0);
                a1 = __shfl_sync(0xFFFFFFFFu, accR[1], s0);
                a2 = __shfl_sync(0xFFFFFFFFu, accR[2], s0);
                a3 = __shfl_sync(0xFFFFFFFFu, accR[3], s0);
                sR.x = hiP ? a2 : a0;  sR.y = hiP ? a3 : a1;
                a0 = __shfl_sync(0xFFFFFFFFu, accR[0], s1);
                a1 = __shfl_sync(0xFFFFFFFFu, accR[1], s1);
                a2 = __shfl_sync(0xFFFFFFFFu, accR[2], s1);
                a3 = __shfl_sync(0xFFFFFFFFu, accR[3], s1);
                sR.z = hiP ? a2 : a0;  sR.w = hiP ? a3 : a1;

                a0 = __shfl_sync(0xFFFFFFFFu, accZ[0], s0);
                a1 = __shfl_sync(0xFFFFFFFFu, accZ[1], s0);
                a2 = __shfl_sync(0xFFFFFFFFu, accZ[2], s0);
                a3 = __shfl_sync(0xFFFFFFFFu, accZ[3], s0);
                sZ.x = hiP ? a2 : a0;  sZ.y = hiP ? a3 : a1;
                a0 = __shfl_sync(0xFFFFFFFFu, accZ[0], s1);
                a1 = __shfl_sync(0xFFFFFFFFu, accZ[1], s1);
                a2 = __shfl_sync(0xFFFFFFFFu, accZ[2], s1);
                a3 = __shfl_sync(0xFFFFFFFFu, accZ[3], s1);
                sZ.z = hiP ? a2 : a0;  sZ.w = hiP ? a3 : a1;

                a0 = __shfl_sync(0xFFFFFFFFu, accN[0], s0);
                a1 = __shfl_sync(0xFFFFFFFFu, accN[1], s0);
                a2 = __shfl_sync(0xFFFFFFFFu, accN[2], s0);
                a3 = __shfl_sync(0xFFFFFFFFu, accN[3], s0);
                sN.x = hiP ? a2 : a0;  sN.y = hiP ? a3 : a1;
                a0 = __shfl_sync(0xFFFFFFFFu, accN[0], s1);
                a1 = __shfl_sync(0xFFFFFFFFu, accN[1], s1);
                a2 = __shfl_sync(0xFFFFFFFFu, accN[2], s1);
                a3 = __shfl_sync(0xFFFFFFFFu, accN[3], s1);
                sN.z = hiP ? a2 : a0;  sN.w = hiP ? a3 : a1;
            }

            // gating (hold = own registers)
            {
                float r, z, n;
                r = sigmoidf_fast(gir.x + sR.x);
                z = sigmoidf_fast(giz.x + sZ.x);
                n = tanhf(gin.x + r * (sN.x + bn4.x));
                hn[g][0] = n + z * (hn[g][0] - n);
                r = sigmoidf_fast(gir.y + sR.y);
                z = sigmoidf_fast(giz.y + sZ.y);
                n = tanhf(gin.y + r * (sN.y + bn4.y));
                hn[g][1] = n + z * (hn[g][1] - n);
                r = sigmoidf_fast(gir.z + sR.z);
                z = sigmoidf_fast(giz.z + sZ.z);
                n = tanhf(gin.z + r * (sN.z + bn4.z));
                hn[g][2] = n + z * (hn[g][2] - n);
                r = sigmoidf_fast(gir.w + sR.w);
                z = sigmoidf_fast(giz.w + sZ.w);
                n = tanhf(gin.w + r * (sN.w + bn4.w));
                hn[g][3] = n + z * (hn[g][3] - n);
            }

            if (layer == 0) {
                *reinterpret_cast<float4*>(
                    &g_H1[((size_t)t * BB + b0 + g * 16 + pb) * (2 * HH) + (size_t)d * HH + jg4]) =
                    make_float4(hn[g][0], hn[g][1], hn[g][2], hn[g][3]);
            }

            // ---- store phase ----
            if (s + 1 < TT) {
                __nv_bfloat16 b0h = __float2bfloat16(hn[g][0]);
                __nv_bfloat16 b1h = __float2bfloat16(hn[g][1]);
                __nv_bfloat16 b2h = __float2bfloat16(hn[g][2]);
                __nv_bfloat16 b3h = __float2bfloat16(hn[g][3]);
                unsigned hiw0 = ((unsigned)__bfloat16_as_ushort(b1h) << 16) | __bfloat16_as_ushort(b0h);
                unsigned hiw1 = ((unsigned)__bfloat16_as_ushort(b3h) << 16) | __bfloat16_as_ushort(b2h);
                __nv_bfloat16 b0l = __float2bfloat16(hn[g][0] - __bfloat162float(b0h));
                __nv_bfloat16 b1l = __float2bfloat16(hn[g][1] - __bfloat162float(b1h));
                __nv_bfloat16 b2l = __float2bfloat16(hn[g][2] - __bfloat162float(b2h));
                __nv_bfloat16 b3l = __float2bfloat16(hn[g][3] - __bfloat162float(b3h));
                unsigned low0 = ((unsigned)__bfloat16_as_ushort(b1l) << 16) | __bfloat16_as_ushort(b0l);
                unsigned low1 = ((unsigned)__bfloat16_as_ushort(b3l) << 16) | __bfloat16_as_ushort(b2l);

                mbar_wait_cluster(mbR_l, s & 1);   // all ranks done reading h_g(s)

                unsigned ohi = hoff + hw0 * 4u;
                unsigned olo = ohi + HPL;
#pragma unroll
                for (int rkt = 0; rkt < 4; rkt++) {
                    unsigned base = ra[rkt];
                    asm volatile("st.shared::cluster.b32 [%0], %1;" :: "r"(base + ohi),     "r"(hiw0) : "memory");
                    asm volatile("st.shared::cluster.b32 [%0], %1;" :: "r"(base + ohi + 4), "r"(hiw1) : "memory");
                    asm volatile("st.shared::cluster.b32 [%0], %1;" :: "r"(base + olo),     "r"(low0) : "memory");
                    asm volatile("st.shared::cluster.b32 [%0], %1;" :: "r"(base + olo + 4), "r"(low1) : "memory");
                }

                __syncthreads();   // all threads' remote stores issued
                if (tid == 0) {
                    asm volatile("fence.acq_rel.cluster;" ::: "memory");
                    mbar_arrive_rank(wr0[g]);
                    mbar_arrive_rank(wr1[g]);
                    mbar_arrive_rank(wr2[g]);
                    mbar_arrive_rank(wr3[g]);
                }
            }
        }
    }

    if (layer != 0) {
#pragma unroll
        for (int g = 0; g < 2; g++) {
            *reinterpret_cast<float4*>(
                &fin[(size_t)(b0 + g * 16 + pb) * (2 * HH) + (size_t)d * HH + jg4]) =
                make_float4(hn[g][0], hn[g][1], hn[g][2], hn[g][3]);
        }
    }

    CLUSTER_SYNC_();   // exit safety (DSMEM stores in flight)
}

// ---------------- launch ----------------
extern "C" void kernel_launch(void* const* d_in, const int* in_sizes, int n_in,
                              void* d_out, int out_size) {
    (void)in_sizes; (void)n_in; (void)out_size;
    const float* x     = (const float*)d_in[0];
    const float* w_ih0 = (const float*)d_in[1];
    const float* w_hh0 = (const float*)d_in[2];
    const float* b_ih0 = (const float*)d_in[3];
    const float* b_hh0 = (const float*)d_in[4];
    const float* w_ih1 = (const float*)d_in[5];
    const float* w_hh1 = (const float*)d_in[6];
    const float* b_ih1 = (const float*)d_in[7];
    const float* b_hh1 = (const float*)d_in[8];
    float* out = (float*)d_out;

    cudaFuncSetAttribute(gru_scan_mma, cudaFuncAttributeMaxDynamicSharedMemorySize, SMEM_SCAN);

    // order (harness prepends 2): transpose=2, prep=3, gemm0=4, scan0=5 <- ncu -s 5
    transpose_x<<<(BB * TT * (DD / 4) + 255) / 256, 256>>>(x);
    prep_wsplit<<<(16 * 24576 + 255) / 256, 256>>>(w_hh0, w_hh1);

    dim3 gg(512, 6, 2);
    gemm_tf32<<<gg, 256>>>(0, w_ih0, b_ih0, b_hh0);
    gru_scan_mma<<<64, 256, SMEM_SCAN>>>(0, b_hh0, nullptr);   // 16 clusters x 4 CTAs
    gemm_tf32<<<gg, 256>>>(1, w_ih1, b_ih1, b_hh1);
    gru_scan_mma<<<64, 256, SMEM_SCAN>>>(1, b_hh1, out);
}

// round 16
// speedup vs baseline: 1.5757x; 1.5757x over previous
#include <cuda_runtime.h>
#include <cuda_bf16.h>
#include <cstdint>

#define BB 256
#define TT 256
#define DD 64
#define HH 256
#define GG 768

// ---------------- scratch ----------------
__device__ float    g_XT[TT * BB * DD];
__device__ float    g_H1[TT * BB * 2 * HH];
__device__ float    g_GI[2 * TT * BB * GG];
__device__ unsigned g_Whi[16 * 24576];   // [l*2+d][rank] -> frag-ordered bf16x2 words (hi)
__device__ unsigned g_Wlo[16 * 24576];   // (lo)

// ---------------- helpers ----------------
__device__ __forceinline__ float sigmoidf_fast(float x) {
    return 1.0f / (1.0f + __expf(-x));
}
__device__ __forceinline__ unsigned cvt_tf32(float f) {
    unsigned r;
    asm volatile("cvt.rna.tf32.f32 %0, %1;" : "=r"(r) : "f"(f));
    return r;
}
__device__ __forceinline__ unsigned mapa_sh(unsigned addr, unsigned rnk) {
    unsigned ra;
    asm volatile("mapa.shared::cluster.u32 %0, %1, %2;" : "=r"(ra) : "r"(addr), "r"(rnk));
    return ra;
}
#define CLUSTER_SYNC_() \
    asm volatile("barrier.cluster.arrive.aligned;\n\tbarrier.cluster.wait.aligned;" ::: "memory")

__device__ __forceinline__ void mbar_init(unsigned addr, unsigned cnt) {
    asm volatile("mbarrier.init.shared.b64 [%0], %1;" :: "r"(addr), "r"(cnt) : "memory");
}
__device__ __forceinline__ void mbar_arrive_rank(unsigned remaddr) {
    asm volatile("mbarrier.arrive.shared::cluster.b64 _, [%0];" :: "r"(remaddr) : "memory");
}
__device__ __forceinline__ void mbar_wait_cluster(unsigned addr, unsigned parity) {
    unsigned done;
    do {
        asm volatile(
            "{\n\t.reg .pred p;\n\t"
            "mbarrier.try_wait.parity.acquire.cluster.shared::cta.b64 p, [%1], %2, 0x989680;\n\t"
            "selp.b32 %0, 1, 0, p;\n\t}"
            : "=r"(done) : "r"(addr), "r"(parity) : "memory");
    } while (!done);
}

__device__ __forceinline__ void mma_tf32(float* acc, const unsigned* a, unsigned b0, unsigned b1) {
    asm volatile(
        "mma.sync.aligned.m16n8k8.row.col.f32.tf32.tf32.f32 "
        "{%0,%1,%2,%3}, {%4,%5,%6,%7}, {%8,%9}, {%0,%1,%2,%3};\n"
        : "+f"(acc[0]), "+f"(acc[1]), "+f"(acc[2]), "+f"(acc[3])
        : "r"(a[0]), "r"(a[1]), "r"(a[2]), "r"(a[3]), "r"(b0), "r"(b1));
}
__device__ __forceinline__ void mma_bf16(float* acc, const unsigned* a, unsigned b0, unsigned b1) {
    asm volatile(
        "mma.sync.aligned.m16n8k16.row.col.f32.bf16.bf16.f32 "
        "{%0,%1,%2,%3}, {%4,%5,%6,%7}, {%8,%9}, {%0,%1,%2,%3};\n"
        : "+f"(acc[0]), "+f"(acc[1]), "+f"(acc[2]), "+f"(acc[3])
        : "r"(a[0]), "r"(a[1]), "r"(a[2]), "r"(a[3]), "r"(b0), "r"(b1));
}

// ---------------- transpose x ----------------
__global__ void transpose_x(const float* __restrict__ x) {
    int i = blockIdx.x * blockDim.x + threadIdx.x;
    if (i >= BB * TT * (DD / 4)) return;
    int d4 = i & 15;
    int t  = (i >> 4) & 255;
    int b  = i >> 12;
    const float4* src = reinterpret_cast<const float4*>(x);
    float4* dst = reinterpret_cast<float4*>(g_XT);
    dst[((t * BB + b) * (DD / 4)) + d4] = src[((b * TT + t) * (DD / 4)) + d4];
}

// ---------------- prep: split w_hh into fragment-ordered bf16 hi/lo planes ----------------
__global__ void prep_wsplit(const float* __restrict__ w0, const float* __restrict__ w1) {
    int i = blockIdx.x * blockDim.x + threadIdx.x;
    if (i >= 16 * 24576) return;
    int w64  = i & 63;
    int blk  = i >> 6;
    int kf   = blk & 15;
    int gfid = blk >> 4;
    int gf   = gfid % 24;
    int ldr  = gfid / 24;
    int rank = ldr & 3;
    int d    = (ldr >> 2) & 1;
    int l    = ldr >> 3;
    int g    = gf >> 3;
    int f    = gf & 7;
    int lane = w64 >> 1;
    int r    = w64 & 1;
    int row  = g * 256 + rank * 64 + f * 8 + (lane >> 2);
    int k    = kf * 16 + (lane & 3) * 2 + r * 8;
    const float* w = l ? w1 : w0;
    const float* p = w + ((size_t)d * GG + row) * HH + k;
    float v0 = p[0], v1 = p[1];
    __nv_bfloat16 h0 = __float2bfloat16(v0);
    __nv_bfloat16 h1 = __float2bfloat16(v1);
    __nv_bfloat16 l0 = __float2bfloat16(v0 - __bfloat162float(h0));
    __nv_bfloat16 l1 = __float2bfloat16(v1 - __bfloat162float(h1));
    g_Whi[i] = ((unsigned)__bfloat16_as_ushort(h1) << 16) | __bfloat16_as_ushort(h0);
    g_Wlo[i] = ((unsigned)__bfloat16_as_ushort(l1) << 16) | __bfloat16_as_ushort(l0);
}

// ---------------- gi GEMM: tf32x3, 128x128 tiles (validated, unchanged) ----------------
#define Bb_M 128
#define Bb_N 128
#define Bb_K 16
#define SSTR 20

__global__ void __launch_bounds__(256) gemm_tf32(int layer,
                                                 const float* __restrict__ Wih,
                                                 const float* __restrict__ bih,
                                                 const float* __restrict__ bhh) {
    __shared__ float sA[2][Bb_M * SSTR];
    __shared__ float sB[2][Bb_N * SSTR];

    const float* A = layer ? g_H1 : g_XT;
    const int K    = layer ? 512 : 64;
    float* C = g_GI;

    int tid  = threadIdx.x;
    int m0   = blockIdx.x * Bb_M;
    int n0   = blockIdx.y * Bb_N;
    int d    = blockIdx.z;
    const float* Ab = A + (size_t)m0 * K;
    const float* Wb = Wih + ((size_t)d * GG + n0) * K;
    float* Cb = C + (size_t)d * (TT * BB) * GG;

    int lane = tid & 31, wid = tid >> 5;
    int wm = wid & 3, wn = wid >> 2;

    float acc[2][8][4];
#pragma unroll
    for (int a = 0; a < 2; a++)
#pragma unroll
        for (int b = 0; b < 8; b++)
#pragma unroll
            for (int c = 0; c < 4; c++) acc[a][b][c] = 0.0f;

    auto load_tile = [&](int kt, int buf) {
        int k0 = kt * Bb_K;
#pragma unroll
        for (int i = 0; i < 2; i++) {
            int s   = tid * 2 + i;
            int row = s >> 2;
            int seg = s & 3;
            unsigned da = (unsigned)__cvta_generic_to_shared(&sA[buf][row * SSTR + seg * 4]);
            const float* ga = Ab + (size_t)row * K + k0 + seg * 4;
            asm volatile("cp.async.cg.shared.global [%0], [%1], 16;\n" :: "r"(da), "l"(ga));
            unsigned db = (unsigned)__cvta_generic_to_shared(&sB[buf][row * SSTR + seg * 4]);
            const float* gb = Wb + (size_t)row * K + k0 + seg * 4;
            asm volatile("cp.async.cg.shared.global [%0], [%1], 16;\n" :: "r"(db), "l"(gb));
        }
        asm volatile("cp.async.commit_group;\n" ::: "memory");
    };

    const int KT = K / Bb_K;
    load_tile(0, 0);
    for (int kt = 0; kt < KT; kt++) {
        int buf = kt & 1;
        if (kt + 1 < KT) {
            load_tile(kt + 1, buf ^ 1);
            asm volatile("cp.async.wait_group 1;\n" ::: "memory");
        } else {
            asm volatile("cp.async.wait_group 0;\n" ::: "memory");
        }
        __syncthreads();
        const float* a_s = sA[buf];
        const float* b_s = sB[buf];
#pragma unroll
        for (int ks = 0; ks < 2; ks++) {
            int kk = ks * 8;
            unsigned ahi[2][4], alo[2][4];
#pragma unroll
            for (int mf = 0; mf < 2; mf++) {
                const float* p = a_s + (wm * 32 + mf * 16 + (lane >> 2)) * SSTR + kk + (lane & 3);
                float f0 = p[0];
                float f1 = p[8 * SSTR];
                float f2 = p[4];
                float f3 = p[8 * SSTR + 4];
                ahi[mf][0] = cvt_tf32(f0); alo[mf][0] = __float_as_uint(f0 - __uint_as_float(ahi[mf][0]));
                ahi[mf][1] = cvt_tf32(f1); alo[mf][1] = __float_as_uint(f1 - __uint_as_float(ahi[mf][1]));
                ahi[mf][2] = cvt_tf32(f2); alo[mf][2] = __float_as_uint(f2 - __uint_as_float(ahi[mf][2]));
                ahi[mf][3] = cvt_tf32(f3); alo[mf][3] = __float_as_uint(f3 - __uint_as_float(ahi[mf][3]));
            }
#pragma unroll
            for (int nf = 0; nf < 8; nf++) {
                const float* p = b_s + (wn * 64 + nf * 8 + (lane >> 2)) * SSTR + kk + (lane & 3);
                float g0 = p[0];
                float g1 = p[4];
                unsigned bhi0 = cvt_tf32(g0), blo0 = __float_as_uint(g0 - __uint_as_float(bhi0));
                unsigned bhi1 = cvt_tf32(g1), blo1 = __float_as_uint(g1 - __uint_as_float(bhi1));
#pragma unroll
                for (int mf = 0; mf < 2; mf++) {
                    mma_tf32(acc[mf][nf], ahi[mf], bhi0, bhi1);
                    mma_tf32(acc[mf][nf], ahi[mf], blo0, blo1);
                    mma_tf32(acc[mf][nf], alo[mf], bhi0, bhi1);
                }
            }
        }
        __syncthreads();
    }

#pragma unroll
    for (int mf = 0; mf < 2; mf++)
#pragma unroll
        for (int nf = 0; nf < 8; nf++)
#pragma unroll
            for (int i = 0; i < 4; i++) {
                int row = m0 + wm * 32 + mf * 16 + (lane >> 2) + ((i >> 1) ? 8 : 0);
                int col = n0 + wn * 64 + nf * 8 + (lane & 3) * 2 + (i & 1);
                float bias = __ldg(&bih[d * GG + col]) +
                             (col < 2 * HH ? __ldg(&bhh[d * GG + col]) : 0.0f);
                Cb[(size_t)row * GG + col] = acc[mf][nf][i] + bias;
            }
}

// ---------------- GRU scan v6b: v6 (4605us winner) + b64 DSMEM stores ----------------
#define WPL_W   24576
#define APL_W   (16 * 132)
#define WH_OFF  0
#define WL_OFF  (WPL_W * 4)                // 98304
#define AHI_OFF (2 * WPL_W * 4)            // 196608
#define ALO_OFF (AHI_OFF + APL_W * 4)      // 205056
#define STG_OFF (ALO_OFF + APL_W * 4)      // 213504
#define WSTG 68
#define MB_OFF  (STG_OFF + 3 * 16 * WSTG * 4)   // 226560; bar_reads @ +0, bar_writes @ +8
#define SMEM_SCAN (MB_OFF + 16)                 // 226576

__global__ void __launch_bounds__(256, 1) __cluster_dims__(4, 1, 1)
gru_scan_mma(int layer, const float* __restrict__ bhh, float* __restrict__ fin) {
    extern __shared__ char smem[];
    unsigned* Wh  = reinterpret_cast<unsigned*>(smem + WH_OFF);
    unsigned* Wl  = reinterpret_cast<unsigned*>(smem + WL_OFF);
    unsigned* hhi = reinterpret_cast<unsigned*>(smem + AHI_OFF);
    unsigned* hlo = reinterpret_cast<unsigned*>(smem + ALO_OFF);
    float*    stg = reinterpret_cast<float*>(smem + STG_OFF);

    int tid  = threadIdx.x;
    int lane = tid & 31;
    int w    = tid >> 5;
    int rank = blockIdx.x & 3;
    int cid  = blockIdx.x >> 2;
    int d    = cid & 1;
    int b0   = (cid >> 1) * 16;

    // load W planes
    {
        const uint4* shi = reinterpret_cast<const uint4*>(g_Whi + (size_t)((layer * 2 + d) * 4 + rank) * WPL_W);
        const uint4* slo = reinterpret_cast<const uint4*>(g_Wlo + (size_t)((layer * 2 + d) * 4 + rank) * WPL_W);
        uint4* dhi = reinterpret_cast<uint4*>(Wh);
        uint4* dlo = reinterpret_cast<uint4*>(Wl);
#pragma unroll 4
        for (int i = tid; i < WPL_W / 4; i += 256) { dhi[i] = shi[i]; dlo[i] = slo[i]; }
    }
    for (int i = tid; i < APL_W; i += 256) { hhi[i] = 0u; hlo[i] = 0u; }

    unsigned smbase = (unsigned)__cvta_generic_to_shared(smem);
    unsigned mb_reads_l  = smbase + MB_OFF;
    unsigned mb_writes_l = smbase + MB_OFF + 8;
    if (tid == 0) {
        mbar_init(mb_reads_l, 4);
        mbar_init(mb_writes_l, 4);
    }

    int pb  = tid >> 4;
    int jl4 = (tid & 15) * 4;
    int jg4 = rank * 64 + jl4;
    float4 bn4 = *reinterpret_cast<const float4*>(&bhh[d * GG + 2 * HH + jg4]);

    CLUSTER_SYNC_();   // once: smem init + mbarrier init visible cluster-wide

    unsigned ra0 = mapa_sh(smbase, 0);
    unsigned ra1 = mapa_sh(smbase, 1);
    unsigned ra2 = mapa_sh(smbase, 2);
    unsigned ra3 = mapa_sh(smbase, 3);

    unsigned rdb0 = ra0 + MB_OFF,     rdb1 = ra1 + MB_OFF,
             rdb2 = ra2 + MB_OFF,     rdb3 = ra3 + MB_OFF;
    unsigned wrb0 = ra0 + MB_OFF + 8, wrb1 = ra1 + MB_OFF + 8,
             wrb2 = ra2 + MB_OFF + 8, wrb3 = ra3 + MB_OFF + 8;

    int ar = lane >> 2;
    int aw = ar * 132 + (lane & 3);
    int bR = ((0 * 8 + w) * 16) * 64 + lane * 2;
    int bZ = ((1 * 8 + w) * 16) * 64 + lane * 2;
    int bN = ((2 * 8 + w) * 16) * 64 + lane * 2;

    unsigned hw0 = (unsigned)(pb * 132 + (jg4 >> 1));   // even -> 8B aligned offsets

    float hn0 = 0.f, hn1 = 0.f, hn2 = 0.f, hn3 = 0.f;

    for (int s = 0; s < TT; s++) {
        if (s) mbar_wait_cluster(mb_writes_l, (s & 1) ^ 1);   // h(s) visible everywhere

        int t = d ? (TT - 1 - s) : s;

        const float* gib = g_GI + ((size_t)d * (TT * BB) + (size_t)t * BB + b0 + pb) * GG;
        float4 gir = *reinterpret_cast<const float4*>(gib + jg4);
        float4 giz = *reinterpret_cast<const float4*>(gib + 256 + jg4);
        float4 gin = *reinterpret_cast<const float4*>(gib + 512 + jg4);

        // ---- phase 1: bf16x2 mma over k=256 ----
        float accR[4] = {0.f, 0.f, 0.f, 0.f};
        float accZ[4] = {0.f, 0.f, 0.f, 0.f};
        float accN[4] = {0.f, 0.f, 0.f, 0.f};

#pragma unroll
        for (int kf = 0; kf < 16; kf++) {
            unsigned ahi[4], alo[4];
            ahi[0] = hhi[aw + kf * 8];
            ahi[1] = hhi[aw + kf * 8 + 1056];
            ahi[2] = hhi[aw + kf * 8 + 4];
            ahi[3] = hhi[aw + kf * 8 + 1060];
            alo[0] = hlo[aw + kf * 8];
            alo[1] = hlo[aw + kf * 8 + 1056];
            alo[2] = hlo[aw + kf * 8 + 4];
            alo[3] = hlo[aw + kf * 8 + 1060];

            uint2 bh, bl;
            bh = *reinterpret_cast<const uint2*>(&Wh[bR + kf * 64]);
            bl = *reinterpret_cast<const uint2*>(&Wl[bR + kf * 64]);
            mma_bf16(accR, ahi, bh.x, bh.y);
            mma_bf16(accR, ahi, bl.x, bl.y);
            mma_bf16(accR, alo, bh.x, bh.y);

            bh = *reinterpret_cast<const uint2*>(&Wh[bZ + kf * 64]);
            bl = *reinterpret_cast<const uint2*>(&Wl[bZ + kf * 64]);
            mma_bf16(accZ, ahi, bh.x, bh.y);
            mma_bf16(accZ, ahi, bl.x, bl.y);
            mma_bf16(accZ, alo, bh.x, bh.y);

            bh = *reinterpret_cast<const uint2*>(&Wh[bN + kf * 64]);
            bl = *reinterpret_cast<const uint2*>(&Wl[bN + kf * 64]);
            mma_bf16(accN, ahi, bh.x, bh.y);
            mma_bf16(accN, ahi, bl.x, bl.y);
            mma_bf16(accN, alo, bh.x, bh.y);
        }

        // stage accs (validated epilogue formula)
#pragma unroll
        for (int i = 0; i < 4; i++) {
            int row = ar + ((i >> 1) ? 8 : 0);
            int col = w * 8 + (lane & 3) * 2 + (i & 1);
            stg[(0 * 16 + row) * WSTG + col] = accR[i];
            stg[(1 * 16 + row) * WSTG + col] = accZ[i];
            stg[(2 * 16 + row) * WSTG + col] = accN[i];
        }
        __syncthreads();   // staging visible + all h-plane reads in this CTA done

        // announce reads-done to all ranks (rendezvous only)
        if (tid == 0 && s + 1 < TT) {
            mbar_arrive_rank(rdb0);
            mbar_arrive_rank(rdb1);
            mbar_arrive_rank(rdb2);
            mbar_arrive_rank(rdb3);
        }

        // ---- phase 2: gating (hold = own registers) ----
        float4 sR = *reinterpret_cast<const float4*>(&stg[(0 * 16 + pb) * WSTG + jl4]);
        float4 sZ = *reinterpret_cast<const float4*>(&stg[(1 * 16 + pb) * WSTG + jl4]);
        float4 sN = *reinterpret_cast<const float4*>(&stg[(2 * 16 + pb) * WSTG + jl4]);

        {
            float r, z, n;
            r = sigmoidf_fast(gir.x + sR.x);
            z = sigmoidf_fast(giz.x + sZ.x);
            n = tanhf(gin.x + r * (sN.x + bn4.x));
            hn0 = n + z * (hn0 - n);
            r = sigmoidf_fast(gir.y + sR.y);
            z = sigmoidf_fast(giz.y + sZ.y);
            n = tanhf(gin.y + r * (sN.y + bn4.y));
            hn1 = n + z * (hn1 - n);
            r = sigmoidf_fast(gir.z + sR.z);
            z = sigmoidf_fast(giz.z + sZ.z);
            n = tanhf(gin.z + r * (sN.z + bn4.z));
            hn2 = n + z * (hn2 - n);
            r = sigmoidf_fast(gir.w + sR.w);
            z = sigmoidf_fast(giz.w + sZ.w);
            n = tanhf(gin.w + r * (sN.w + bn4.w));
            hn3 = n + z * (hn3 - n);
        }

        if (layer == 0) {
            *reinterpret_cast<float4*>(
                &g_H1[((size_t)t * BB + b0 + pb) * (2 * HH) + (size_t)d * HH + jg4]) =
                make_float4(hn0, hn1, hn2, hn3);
        }

        if (s + 1 < TT) {
            // bf16 split + pack into two u64 (one per plane)
            __nv_bfloat16 b0h = __float2bfloat16(hn0);
            __nv_bfloat16 b1h = __float2bfloat16(hn1);
            __nv_bfloat16 b2h = __float2bfloat16(hn2);
            __nv_bfloat16 b3h = __float2bfloat16(hn3);
            unsigned hiw0 = ((unsigned)__bfloat16_as_ushort(b1h) << 16) | __bfloat16_as_ushort(b0h);
            unsigned hiw1 = ((unsigned)__bfloat16_as_ushort(b3h) << 16) | __bfloat16_as_ushort(b2h);
            __nv_bfloat16 b0l = __float2bfloat16(hn0 - __bfloat162float(b0h));
            __nv_bfloat16 b1l = __float2bfloat16(hn1 - __bfloat162float(b1h));
            __nv_bfloat16 b2l = __float2bfloat16(hn2 - __bfloat162float(b2h));
            __nv_bfloat16 b3l = __float2bfloat16(hn3 - __bfloat162float(b3h));
            unsigned low0 = ((unsigned)__bfloat16_as_ushort(b1l) << 16) | __bfloat16_as_ushort(b0l);
            unsigned low1 = ((unsigned)__bfloat16_as_ushort(b3l) << 16) | __bfloat16_as_ushort(b2l);
            unsigned long long hiq, loq;
            asm("mov.b64 %0, {%1, %2};" : "=l"(hiq) : "r"(hiw0), "r"(hiw1));
            asm("mov.b64 %0, {%1, %2};" : "=l"(loq) : "r"(low0), "r"(low1));

            mbar_wait_cluster(mb_reads_l, s & 1);   // every rank done reading h(s)

            unsigned ohi = AHI_OFF + hw0 * 4u;
            unsigned olo = ALO_OFF + hw0 * 4u;
            asm volatile("st.shared::cluster.b64 [%0], %1;" :: "r"(ra0 + ohi), "l"(hiq) : "memory");
            asm volatile("st.shared::cluster.b64 [%0], %1;" :: "r"(ra0 + olo), "l"(loq) : "memory");
            asm volatile("st.shared::cluster.b64 [%0], %1;" :: "r"(ra1 + ohi), "l"(hiq) : "memory");
            asm volatile("st.shared::cluster.b64 [%0], %1;" :: "r"(ra1 + olo), "l"(loq) : "memory");
            asm volatile("st.shared::cluster.b64 [%0], %1;" :: "r"(ra2 + ohi), "l"(hiq) : "memory");
            asm volatile("st.shared::cluster.b64 [%0], %1;" :: "r"(ra2 + olo), "l"(loq) : "memory");
            asm volatile("st.shared::cluster.b64 [%0], %1;" :: "r"(ra3 + ohi), "l"(hiq) : "memory");
            asm volatile("st.shared::cluster.b64 [%0], %1;" :: "r"(ra3 + olo), "l"(loq) : "memory");

            __syncthreads();   // all threads' remote stores issued (happens-before tid0 fence)
            if (tid == 0) {
                asm volatile("fence.acq_rel.cluster;" ::: "memory");
                mbar_arrive_rank(wrb0);
                mbar_arrive_rank(wrb1);
                mbar_arrive_rank(wrb2);
                mbar_arrive_rank(wrb3);
            }
        }
    }

    if (layer != 0) {
        *reinterpret_cast<float4*>(
            &fin[(size_t)(b0 + pb) * (2 * HH) + (size_t)d * HH + jg4]) =
            make_float4(hn0, hn1, hn2, hn3);
    }

    CLUSTER_SYNC_();   // exit safety
}

// ---------------- launch ----------------
extern "C" void kernel_launch(void* const* d_in, const int* in_sizes, int n_in,
                              void* d_out, int out_size) {
    (void)in_sizes; (void)n_in; (void)out_size;
    const float* x     = (const float*)d_in[0];
    const float* w_ih0 = (const float*)d_in[1];
    const float* w_hh0 = (const float*)d_in[2];
    const float* b_ih0 = (const float*)d_in[3];
    const float* b_hh0 = (const float*)d_in[4];
    const float* w_ih1 = (const float*)d_in[5];
    const float* w_hh1 = (const float*)d_in[6];
    const float* b_ih1 = (const float*)d_in[7];
    const float* b_hh1 = (const float*)d_in[8];
    float* out = (float*)d_out;

    cudaFuncSetAttribute(gru_scan_mma, cudaFuncAttributeMaxDynamicSharedMemorySize, SMEM_SCAN);

    // order (harness prepends 2): transpose=2, prep=3, gemm0=4, scan0=5 <- ncu -s 5
    transpose_x<<<(BB * TT * (DD / 4) + 255) / 256, 256>>>(x);
    prep_wsplit<<<(16 * 24576 + 255) / 256, 256>>>(w_hh0, w_hh1);

    dim3 gg(512, 6, 2);
    gemm_tf32<<<gg, 256>>>(0, w_ih0, b_ih0, b_hh0);
    gru_scan_mma<<<128, 256, SMEM_SCAN>>>(0, b_hh0, nullptr);
    gemm_tf32<<<gg, 256>>>(1, w_ih1, b_ih1, b_hh1);
    gru_scan_mma<<<128, 256, SMEM_SCAN>>>(1, b_hh1, out);
}

// round 17
// speedup vs baseline: 1.6842x; 1.0689x over previous
#include <cuda_runtime.h>
#include <cuda_bf16.h>
#include <cstdint>

#define BB 256
#define TT 256
#define DD 64
#define HH 256
#define GG 768

// ---------------- scratch ----------------
__device__ float    g_XT[TT * BB * DD];
__device__ float    g_H1[TT * BB * 2 * HH];
__device__ float    g_GI[2 * TT * BB * GG];
__device__ unsigned g_Whi[16 * 24576];   // [l*2+d][rank] -> frag-ordered bf16x2 words (hi)
__device__ unsigned g_Wlo[16 * 24576];   // (lo)

// ---------------- helpers ----------------
__device__ __forceinline__ float sigmoidf_fast(float x) {
    return 1.0f / (1.0f + __expf(-x));
}
__device__ __forceinline__ unsigned cvt_tf32(float f) {
    unsigned r;
    asm volatile("cvt.rna.tf32.f32 %0, %1;" : "=r"(r) : "f"(f));
    return r;
}
__device__ __forceinline__ unsigned mapa_sh(unsigned addr, unsigned rnk) {
    unsigned ra;
    asm volatile("mapa.shared::cluster.u32 %0, %1, %2;" : "=r"(ra) : "r"(addr), "r"(rnk));
    return ra;
}
#define CLUSTER_SYNC_() \
    asm volatile("barrier.cluster.arrive.aligned;\n\tbarrier.cluster.wait.aligned;" ::: "memory")

__device__ __forceinline__ void mbar_init(unsigned addr, unsigned cnt) {
    asm volatile("mbarrier.init.shared.b64 [%0], %1;" :: "r"(addr), "r"(cnt) : "memory");
}
__device__ __forceinline__ void mbar_arrive_rank(unsigned remaddr) {
    asm volatile("mbarrier.arrive.shared::cluster.b64 _, [%0];" :: "r"(remaddr) : "memory");
}
__device__ __forceinline__ void mbar_wait_cluster(unsigned addr, unsigned parity) {
    unsigned done;
    do {
        asm volatile(
            "{\n\t.reg .pred p;\n\t"
            "mbarrier.try_wait.parity.acquire.cluster.shared::cta.b64 p, [%1], %2, 0x989680;\n\t"
            "selp.b32 %0, 1, 0, p;\n\t}"
            : "=r"(done) : "r"(addr), "r"(parity) : "memory");
    } while (!done);
}

__device__ __forceinline__ void mma_tf32(float* acc, const unsigned* a, unsigned b0, unsigned b1) {
    asm volatile(
        "mma.sync.aligned.m16n8k8.row.col.f32.tf32.tf32.f32 "
        "{%0,%1,%2,%3}, {%4,%5,%6,%7}, {%8,%9}, {%0,%1,%2,%3};\n"
        : "+f"(acc[0]), "+f"(acc[1]), "+f"(acc[2]), "+f"(acc[3])
        : "r"(a[0]), "r"(a[1]), "r"(a[2]), "r"(a[3]), "r"(b0), "r"(b1));
}
__device__ __forceinline__ void mma_bf16(float* acc, const unsigned* a, unsigned b0, unsigned b1) {
    asm volatile(
        "mma.sync.aligned.m16n8k16.row.col.f32.bf16.bf16.f32 "
        "{%0,%1,%2,%3}, {%4,%5,%6,%7}, {%8,%9}, {%0,%1,%2,%3};\n"
        : "+f"(acc[0]), "+f"(acc[1]), "+f"(acc[2]), "+f"(acc[3])
        : "r"(a[0]), "r"(a[1]), "r"(a[2]), "r"(a[3]), "r"(b0), "r"(b1));
}

// ---------------- transpose x ----------------
__global__ void transpose_x(const float* __restrict__ x) {
    int i = blockIdx.x * blockDim.x + threadIdx.x;
    if (i >= BB * TT * (DD / 4)) return;
    int d4 = i & 15;
    int t  = (i >> 4) & 255;
    int b  = i >> 12;
    const float4* src = reinterpret_cast<const float4*>(x);
    float4* dst = reinterpret_cast<float4*>(g_XT);
    dst[((t * BB + b) * (DD / 4)) + d4] = src[((b * TT + t) * (DD / 4)) + d4];
}

// ---------------- prep: split w_hh into fragment-ordered bf16 hi/lo planes ----------------
__global__ void prep_wsplit(const float* __restrict__ w0, const float* __restrict__ w1) {
    int i = blockIdx.x * blockDim.x + threadIdx.x;
    if (i >= 16 * 24576) return;
    int w64  = i & 63;
    int blk  = i >> 6;
    int kf   = blk & 15;
    int gfid = blk >> 4;
    int gf   = gfid % 24;
    int ldr  = gfid / 24;
    int rank = ldr & 3;
    int d    = (ldr >> 2) & 1;
    int l    = ldr >> 3;
    int g    = gf >> 3;
    int f    = gf & 7;
    int lane = w64 >> 1;
    int r    = w64 & 1;
    int row  = g * 256 + rank * 64 + f * 8 + (lane >> 2);
    int k    = kf * 16 + (lane & 3) * 2 + r * 8;
    const float* w = l ? w1 : w0;
    const float* p = w + ((size_t)d * GG + row) * HH + k;
    float v0 = p[0], v1 = p[1];
    __nv_bfloat16 h0 = __float2bfloat16(v0);
    __nv_bfloat16 h1 = __float2bfloat16(v1);
    __nv_bfloat16 l0 = __float2bfloat16(v0 - __bfloat162float(h0));
    __nv_bfloat16 l1 = __float2bfloat16(v1 - __bfloat162float(h1));
    g_Whi[i] = ((unsigned)__bfloat16_as_ushort(h1) << 16) | __bfloat16_as_ushort(h0);
    g_Wlo[i] = ((unsigned)__bfloat16_as_ushort(l1) << 16) | __bfloat16_as_ushort(l0);
}

// ---------------- gi GEMM: tf32x3, 128x128 tiles ----------------
// Grid swapped to (n=6, m=512, d): consecutive blocks share the same A m-tile
// across all 6 n-columns -> A read from DRAM once per wave, hit in L2 after.
// C written with __stcs (streaming) so the C stream doesn't evict shared A tiles.
#define Bb_M 128
#define Bb_N 128
#define Bb_K 16
#define SSTR 20

__global__ void __launch_bounds__(256) gemm_tf32(int layer,
                                                 const float* __restrict__ Wih,
                                                 const float* __restrict__ bih,
                                                 const float* __restrict__ bhh) {
    __shared__ float sA[2][Bb_M * SSTR];
    __shared__ float sB[2][Bb_N * SSTR];

    const float* A = layer ? g_H1 : g_XT;
    const int K    = layer ? 512 : 64;
    float* C = g_GI;

    int tid  = threadIdx.x;
    int n0   = blockIdx.x * Bb_N;          // swapped: x = n (6)
    int m0   = blockIdx.y * Bb_M;          //          y = m (512)
    int d    = blockIdx.z;
    const float* Ab = A + (size_t)m0 * K;
    const float* Wb = Wih + ((size_t)d * GG + n0) * K;
    float* Cb = C + (size_t)d * (TT * BB) * GG;

    int lane = tid & 31, wid = tid >> 5;
    int wm = wid & 3, wn = wid >> 2;

    float acc[2][8][4];
#pragma unroll
    for (int a = 0; a < 2; a++)
#pragma unroll
        for (int b = 0; b < 8; b++)
#pragma unroll
            for (int c = 0; c < 4; c++) acc[a][b][c] = 0.0f;

    auto load_tile = [&](int kt, int buf) {
        int k0 = kt * Bb_K;
#pragma unroll
        for (int i = 0; i < 2; i++) {
            int s   = tid * 2 + i;
            int row = s >> 2;
            int seg = s & 3;
            unsigned da = (unsigned)__cvta_generic_to_shared(&sA[buf][row * SSTR + seg * 4]);
            const float* ga = Ab + (size_t)row * K + k0 + seg * 4;
            asm volatile("cp.async.cg.shared.global [%0], [%1], 16;\n" :: "r"(da), "l"(ga));
            unsigned db = (unsigned)__cvta_generic_to_shared(&sB[buf][row * SSTR + seg * 4]);
            const float* gb = Wb + (size_t)row * K + k0 + seg * 4;
            asm volatile("cp.async.cg.shared.global [%0], [%1], 16;\n" :: "r"(db), "l"(gb));
        }
        asm volatile("cp.async.commit_group;\n" ::: "memory");
    };

    const int KT = K / Bb_K;
    load_tile(0, 0);
    for (int kt = 0; kt < KT; kt++) {
        int buf = kt & 1;
        if (kt + 1 < KT) {
            load_tile(kt + 1, buf ^ 1);
            asm volatile("cp.async.wait_group 1;\n" ::: "memory");
        } else {
            asm volatile("cp.async.wait_group 0;\n" ::: "memory");
        }
        __syncthreads();
        const float* a_s = sA[buf];
        const float* b_s = sB[buf];
#pragma unroll
        for (int ks = 0; ks < 2; ks++) {
            int kk = ks * 8;
            unsigned ahi[2][4], alo[2][4];
#pragma unroll
            for (int mf = 0; mf < 2; mf++) {
                const float* p = a_s + (wm * 32 + mf * 16 + (lane >> 2)) * SSTR + kk + (lane & 3);
                float f0 = p[0];
                float f1 = p[8 * SSTR];
                float f2 = p[4];
                float f3 = p[8 * SSTR + 4];
                ahi[mf][0] = cvt_tf32(f0); alo[mf][0] = __float_as_uint(f0 - __uint_as_float(ahi[mf][0]));
                ahi[mf][1] = cvt_tf32(f1); alo[mf][1] = __float_as_uint(f1 - __uint_as_float(ahi[mf][1]));
                ahi[mf][2] = cvt_tf32(f2); alo[mf][2] = __float_as_uint(f2 - __uint_as_float(ahi[mf][2]));
                ahi[mf][3] = cvt_tf32(f3); alo[mf][3] = __float_as_uint(f3 - __uint_as_float(ahi[mf][3]));
            }
#pragma unroll
            for (int nf = 0; nf < 8; nf++) {
                const float* p = b_s + (wn * 64 + nf * 8 + (lane >> 2)) * SSTR + kk + (lane & 3);
                float g0 = p[0];
                float g1 = p[4];
                unsigned bhi0 = cvt_tf32(g0), blo0 = __float_as_uint(g0 - __uint_as_float(bhi0));
                unsigned bhi1 = cvt_tf32(g1), blo1 = __float_as_uint(g1 - __uint_as_float(bhi1));
#pragma unroll
                for (int mf = 0; mf < 2; mf++) {
                    mma_tf32(acc[mf][nf], ahi[mf], bhi0, bhi1);
                    mma_tf32(acc[mf][nf], ahi[mf], blo0, blo1);
                    mma_tf32(acc[mf][nf], alo[mf], bhi0, bhi1);
                }
            }
        }
        __syncthreads();
    }

#pragma unroll
    for (int mf = 0; mf < 2; mf++)
#pragma unroll
        for (int nf = 0; nf < 8; nf++)
#pragma unroll
            for (int i = 0; i < 4; i++) {
                int row = m0 + wm * 32 + mf * 16 + (lane >> 2) + ((i >> 1) ? 8 : 0);
                int col = n0 + wn * 64 + nf * 8 + (lane & 3) * 2 + (i & 1);
                float bias = __ldg(&bih[d * GG + col]) +
                             (col < 2 * HH ? __ldg(&bhh[d * GG + col]) : 0.0f);
                __stcs(&Cb[(size_t)row * GG + col], acc[mf][nf][i] + bias);
            }
}

// ---------------- GRU scan v6b: v6 + b64 DSMEM stores (4117us winner, unchanged) ----------
#define WPL_W   24576
#define APL_W   (16 * 132)
#define WH_OFF  0
#define WL_OFF  (WPL_W * 4)                // 98304
#define AHI_OFF (2 * WPL_W * 4)            // 196608
#define ALO_OFF (AHI_OFF + APL_W * 4)      // 205056
#define STG_OFF (ALO_OFF + APL_W * 4)      // 213504
#define WSTG 68
#define MB_OFF  (STG_OFF + 3 * 16 * WSTG * 4)   // 226560; bar_reads @ +0, bar_writes @ +8
#define SMEM_SCAN (MB_OFF + 16)                 // 226576

__global__ void __launch_bounds__(256, 1) __cluster_dims__(4, 1, 1)
gru_scan_mma(int layer, const float* __restrict__ bhh, float* __restrict__ fin) {
    extern __shared__ char smem[];
    unsigned* Wh  = reinterpret_cast<unsigned*>(smem + WH_OFF);
    unsigned* Wl  = reinterpret_cast<unsigned*>(smem + WL_OFF);
    unsigned* hhi = reinterpret_cast<unsigned*>(smem + AHI_OFF);
    unsigned* hlo = reinterpret_cast<unsigned*>(smem + ALO_OFF);
    float*    stg = reinterpret_cast<float*>(smem + STG_OFF);

    int tid  = threadIdx.x;
    int lane = tid & 31;
    int w    = tid >> 5;
    int rank = blockIdx.x & 3;
    int cid  = blockIdx.x >> 2;
    int d    = cid & 1;
    int b0   = (cid >> 1) * 16;

    // load W planes
    {
        const uint4* shi = reinterpret_cast<const uint4*>(g_Whi + (size_t)((layer * 2 + d) * 4 + rank) * WPL_W);
        const uint4* slo = reinterpret_cast<const uint4*>(g_Wlo + (size_t)((layer * 2 + d) * 4 + rank) * WPL_W);
        uint4* dhi = reinterpret_cast<uint4*>(Wh);
        uint4* dlo = reinterpret_cast<uint4*>(Wl);
#pragma unroll 4
        for (int i = tid; i < WPL_W / 4; i += 256) { dhi[i] = shi[i]; dlo[i] = slo[i]; }
    }
    for (int i = tid; i < APL_W; i += 256) { hhi[i] = 0u; hlo[i] = 0u; }

    unsigned smbase = (unsigned)__cvta_generic_to_shared(smem);
    unsigned mb_reads_l  = smbase + MB_OFF;
    unsigned mb_writes_l = smbase + MB_OFF + 8;
    if (tid == 0) {
        mbar_init(mb_reads_l, 4);
        mbar_init(mb_writes_l, 4);
    }

    int pb  = tid >> 4;
    int jl4 = (tid & 15) * 4;
    int jg4 = rank * 64 + jl4;
    float4 bn4 = *reinterpret_cast<const float4*>(&bhh[d * GG + 2 * HH + jg4]);

    CLUSTER_SYNC_();   // once: smem init + mbarrier init visible cluster-wide

    unsigned ra0 = mapa_sh(smbase, 0);
    unsigned ra1 = mapa_sh(smbase, 1);
    unsigned ra2 = mapa_sh(smbase, 2);
    unsigned ra3 = mapa_sh(smbase, 3);

    unsigned rdb0 = ra0 + MB_OFF,     rdb1 = ra1 + MB_OFF,
             rdb2 = ra2 + MB_OFF,     rdb3 = ra3 + MB_OFF;
    unsigned wrb0 = ra0 + MB_OFF + 8, wrb1 = ra1 + MB_OFF + 8,
             wrb2 = ra2 + MB_OFF + 8, wrb3 = ra3 + MB_OFF + 8;

    int ar = lane >> 2;
    int aw = ar * 132 + (lane & 3);
    int bR = ((0 * 8 + w) * 16) * 64 + lane * 2;
    int bZ = ((1 * 8 + w) * 16) * 64 + lane * 2;
    int bN = ((2 * 8 + w) * 16) * 64 + lane * 2;

    unsigned hw0 = (unsigned)(pb * 132 + (jg4 >> 1));   // even -> 8B aligned offsets

    float hn0 = 0.f, hn1 = 0.f, hn2 = 0.f, hn3 = 0.f;

    for (int s = 0; s < TT; s++) {
        if (s) mbar_wait_cluster(mb_writes_l, (s & 1) ^ 1);   // h(s) visible everywhere

        int t = d ? (TT - 1 - s) : s;

        const float* gib = g_GI + ((size_t)d * (TT * BB) + (size_t)t * BB + b0 + pb) * GG;
        float4 gir = *reinterpret_cast<const float4*>(gib + jg4);
        float4 giz = *reinterpret_cast<const float4*>(gib + 256 + jg4);
        float4 gin = *reinterpret_cast<const float4*>(gib + 512 + jg4);

        // ---- phase 1: bf16x2 mma over k=256 ----
        float accR[4] = {0.f, 0.f, 0.f, 0.f};
        float accZ[4] = {0.f, 0.f, 0.f, 0.f};
        float accN[4] = {0.f, 0.f, 0.f, 0.f};

#pragma unroll
        for (int kf = 0; kf < 16; kf++) {
            unsigned ahi[4], alo[4];
            ahi[0] = hhi[aw + kf * 8];
            ahi[1] = hhi[aw + kf * 8 + 1056];
            ahi[2] = hhi[aw + kf * 8 + 4];
            ahi[3] = hhi[aw + kf * 8 + 1060];
            alo[0] = hlo[aw + kf * 8];
            alo[1] = hlo[aw + kf * 8 + 1056];
            alo[2] = hlo[aw + kf * 8 + 4];
            alo[3] = hlo[aw + kf * 8 + 1060];

            uint2 bh, bl;
            bh = *reinterpret_cast<const uint2*>(&Wh[bR + kf * 64]);
            bl = *reinterpret_cast<const uint2*>(&Wl[bR + kf * 64]);
            mma_bf16(accR, ahi, bh.x, bh.y);
            mma_bf16(accR, ahi, bl.x, bl.y);
            mma_bf16(accR, alo, bh.x, bh.y);

            bh = *reinterpret_cast<const uint2*>(&Wh[bZ + kf * 64]);
            bl = *reinterpret_cast<const uint2*>(&Wl[bZ + kf * 64]);
            mma_bf16(accZ, ahi, bh.x, bh.y);
            mma_bf16(accZ, ahi, bl.x, bl.y);
            mma_bf16(accZ, alo, bh.x, bh.y);

            bh = *reinterpret_cast<const uint2*>(&Wh[bN + kf * 64]);
            bl = *reinterpret_cast<const uint2*>(&Wl[bN + kf * 64]);
            mma_bf16(accN, ahi, bh.x, bh.y);
            mma_bf16(accN, ahi, bl.x, bl.y);
            mma_bf16(accN, alo, bh.x, bh.y);
        }

        // stage accs (validated epilogue formula)
#pragma unroll
        for (int i = 0; i < 4; i++) {
            int row = ar + ((i >> 1) ? 8 : 0);
            int col = w * 8 + (lane & 3) * 2 + (i & 1);
            stg[(0 * 16 + row) * WSTG + col] = accR[i];
            stg[(1 * 16 + row) * WSTG + col] = accZ[i];
            stg[(2 * 16 + row) * WSTG + col] = accN[i];
        }
        __syncthreads();   // staging visible + all h-plane reads in this CTA done

        // announce reads-done to all ranks (rendezvous only)
        if (tid == 0 && s + 1 < TT) {
            mbar_arrive_rank(rdb0);
            mbar_arrive_rank(rdb1);
            mbar_arrive_rank(rdb2);
            mbar_arrive_rank(rdb3);
        }

        // ---- phase 2: gating (hold = own registers) ----
        float4 sR = *reinterpret_cast<const float4*>(&stg[(0 * 16 + pb) * WSTG + jl4]);
        float4 sZ = *reinterpret_cast<const float4*>(&stg[(1 * 16 + pb) * WSTG + jl4]);
        float4 sN = *reinterpret_cast<const float4*>(&stg[(2 * 16 + pb) * WSTG + jl4]);

        {
            float r, z, n;
            r = sigmoidf_fast(gir.x + sR.x);
            z = sigmoidf_fast(giz.x + sZ.x);
            n = tanhf(gin.x + r * (sN.x + bn4.x));
            hn0 = n + z * (hn0 - n);
            r = sigmoidf_fast(gir.y + sR.y);
            z = sigmoidf_fast(giz.y + sZ.y);
            n = tanhf(gin.y + r * (sN.y + bn4.y));
            hn1 = n + z * (hn1 - n);
            r = sigmoidf_fast(gir.z + sR.z);
            z = sigmoidf_fast(giz.z + sZ.z);
            n = tanhf(gin.z + r * (sN.z + bn4.z));
            hn2 = n + z * (hn2 - n);
            r = sigmoidf_fast(gir.w + sR.w);
            z = sigmoidf_fast(giz.w + sZ.w);
            n = tanhf(gin.w + r * (sN.w + bn4.w));
            hn3 = n + z * (hn3 - n);
        }

        if (layer == 0) {
            *reinterpret_cast<float4*>(
                &g_H1[((size_t)t * BB + b0 + pb) * (2 * HH) + (size_t)d * HH + jg4]) =
                make_float4(hn0, hn1, hn2, hn3);
        }

        if (s + 1 < TT) {
            // bf16 split + pack into two u64 (one per plane)
            __nv_bfloat16 b0h = __float2bfloat16(hn0);
            __nv_bfloat16 b1h = __float2bfloat16(hn1);
            __nv_bfloat16 b2h = __float2bfloat16(hn2);
            __nv_bfloat16 b3h = __float2bfloat16(hn3);
            unsigned hiw0 = ((unsigned)__bfloat16_as_ushort(b1h) << 16) | __bfloat16_as_ushort(b0h);
            unsigned hiw1 = ((unsigned)__bfloat16_as_ushort(b3h) << 16) | __bfloat16_as_ushort(b2h);
            __nv_bfloat16 b0l = __float2bfloat16(hn0 - __bfloat162float(b0h));
            __nv_bfloat16 b1l = __float2bfloat16(hn1 - __bfloat162float(b1h));
            __nv_bfloat16 b2l = __float2bfloat16(hn2 - __bfloat162float(b2h));
            __nv_bfloat16 b3l = __float2bfloat16(hn3 - __bfloat162float(b3h));
            unsigned low0 = ((unsigned)__bfloat16_as_ushort(b1l) << 16) | __bfloat16_as_ushort(b0l);
            unsigned low1 = ((unsigned)__bfloat16_as_ushort(b3l) << 16) | __bfloat16_as_ushort(b2l);
            unsigned long long hiq, loq;
            asm("mov.b64 %0, {%1, %2};" : "=l"(hiq) : "r"(hiw0), "r"(hiw1));
            asm("mov.b64 %0, {%1, %2};" : "=l"(loq) : "r"(low0), "r"(low1));

            mbar_wait_cluster(mb_reads_l, s & 1);   // every rank done reading h(s)

            unsigned ohi = AHI_OFF + hw0 * 4u;
            unsigned olo = ALO_OFF + hw0 * 4u;
            asm volatile("st.shared::cluster.b64 [%0], %1;" :: "r"(ra0 + ohi), "l"(hiq) : "memory");
            asm volatile("st.shared::cluster.b64 [%0], %1;" :: "r"(ra0 + olo), "l"(loq) : "memory");
            asm volatile("st.shared::cluster.b64 [%0], %1;" :: "r"(ra1 + ohi), "l"(hiq) : "memory");
            asm volatile("st.shared::cluster.b64 [%0], %1;" :: "r"(ra1 + olo), "l"(loq) : "memory");
            asm volatile("st.shared::cluster.b64 [%0], %1;" :: "r"(ra2 + ohi), "l"(hiq) : "memory");
            asm volatile("st.shared::cluster.b64 [%0], %1;" :: "r"(ra2 + olo), "l"(loq) : "memory");
            asm volatile("st.shared::cluster.b64 [%0], %1;" :: "r"(ra3 + ohi), "l"(hiq) : "memory");
            asm volatile("st.shared::cluster.b64 [%0], %1;" :: "r"(ra3 + olo), "l"(loq) : "memory");

            __syncthreads();   // all threads' remote stores issued (happens-before tid0 fence)
            if (tid == 0) {
                asm volatile("fence.acq_rel.cluster;" ::: "memory");
                mbar_arrive_rank(wrb0);
                mbar_arrive_rank(wrb1);
                mbar_arrive_rank(wrb2);
                mbar_arrive_rank(wrb3);
            }
        }
    }

    if (layer != 0) {
        *reinterpret_cast<float4*>(
            &fin[(size_t)(b0 + pb) * (2 * HH) + (size_t)d * HH + jg4]) =
            make_float4(hn0, hn1, hn2, hn3);
    }

    CLUSTER_SYNC_();   // exit safety
}

// ---------------- launch ----------------
extern "C" void kernel_launch(void* const* d_in, const int* in_sizes, int n_in,
                              void* d_out, int out_size) {
    (void)in_sizes; (void)n_in; (void)out_size;
    const float* x     = (const float*)d_in[0];
    const float* w_ih0 = (const float*)d_in[1];
    const float* w_hh0 = (const float*)d_in[2];
    const float* b_ih0 = (const float*)d_in[3];
    const float* b_hh0 = (const float*)d_in[4];
    const float* w_ih1 = (const float*)d_in[5];
    const float* w_hh1 = (const float*)d_in[6];
    const float* b_ih1 = (const float*)d_in[7];
    const float* b_hh1 = (const float*)d_in[8];
    float* out = (float*)d_out;

    cudaFuncSetAttribute(gru_scan_mma, cudaFuncAttributeMaxDynamicSharedMemorySize, SMEM_SCAN);

    // order (harness prepends 2): transpose=2, prep=3, gemm0=4, scan0=5 <- ncu -s 5
    transpose_x<<<(BB * TT * (DD / 4) + 255) / 256, 256>>>(x);
    prep_wsplit<<<(16 * 24576 + 255) / 256, 256>>>(w_hh0, w_hh1);

    dim3 gg(6, 512, 2);   // swapped: x=n (6), y=m (512) -> in-wave A-tile sharing via L2
    gemm_tf32<<<gg, 256>>>(0, w_ih0, b_ih0, b_hh0);
    gru_scan_mma<<<128, 256, SMEM_SCAN>>>(0, b_hh0, nullptr);
    gemm_tf32<<<gg, 256>>>(1, w_ih1, b_ih1, b_hh1);
    gru_scan_mma<<<128, 256, SMEM_SCAN>>>(1, b_hh1, out);
}